// round 16
// baseline (speedup 1.0000x reference)
#include <cuda_runtime.h>
#include <cuda_fp16.h>
#include <math.h>
#include <stdint.h>

// R16: R14 structure (best: 418.5us) + cross-stream overlap.
//  - mlp reverted to R14's 1 pt/thread (R15's 2pt/thread lost occupancy).
//  - Points split into two chunks. Fork-join on a second stream overlaps
//    mlp(chunk0) [FMA-bound, DRAM 23%] with phased(chunk1) [DRAM-bound,
//    fma 5%] -- disjoint resources, per-point dependency honored.
//  - Stream/events are created on the first (uncaptured correctness) call
//    and reused; event fork-join is the documented capture pattern.
// Per-point math bit-identical to R8-R15 -> rel_err stays 6.8627e-4.

#define NLVL   20
#define LOG2T  24
#define TMASK  ((1u << LOG2T) - 1u)
#define PRIME1 2654435761u
#define PRIME2 805459861u
#define INDIM  40
#define HID    64
#define NPTS   524288

struct ResParams { float r[NLVL]; };

__device__ __half2 g_feat[NLVL * NPTS];   // level-major scratch (42 MB)

__device__ __forceinline__ float h_rt(float v) {
    return __half2float(__float2half_rn(v));
}

__device__ __forceinline__ bool probe_f32(const void* W2_) {
    const float* w2p = (const float*)W2_;
    int votes = 0;
    #pragma unroll
    for (int i = 0; i < 8; ++i) {
        const float v = __ldg(w2p + i);
        if (isfinite(v) && fabsf(v) >= 2e-3f && fabsf(v) <= 8.0f) ++votes;
    }
    return votes >= 4;
}

// ---- f32x2 packed helpers (FFMA2) ----
__device__ __forceinline__ uint64_t pk2(float lo, float hi) {
    uint64_t r; asm("mov.b64 %0, {%1,%2};" : "=l"(r) : "f"(lo), "f"(hi)); return r;
}
__device__ __forceinline__ float2 upk2(uint64_t v) {
    float2 f; asm("mov.b64 {%0,%1}, %2;" : "=f"(f.x), "=f"(f.y) : "l"(v)); return f;
}
__device__ __forceinline__ void ffma2(uint64_t& d, uint64_t a, uint64_t b) {
    asm("fma.rn.f32x2 %0, %1, %2, %0;" : "+l"(d) : "l"(a), "l"(b));
}

// ---- one level's gather+interp (bit-identical reference fp16 chain) ----
__device__ __forceinline__ __half2 encode_level(
    float px, float py, float pz, float rf,
    const void* __restrict__ table_, int li, bool f32mode)
{
    const float fx = px * rf, fy = py * rf, fz = pz * rf;
    const float gx = floorf(fx), gy = floorf(fy), gz = floorf(fz);
    const float dx = fx - gx, dy = fy - gy, dz = fz - gz;
    const unsigned bx = (unsigned)gx;
    const unsigned by = (unsigned)gy;
    const unsigned bz = (unsigned)gz;
    const unsigned hy0 = by * PRIME1, hy1 = hy0 + PRIME1;
    const unsigned hz0 = bz * PRIME2, hz1 = hz0 + PRIME2;
    const unsigned bx1 = bx + 1u;

    const unsigned i0 = (bx  ^ hy0 ^ hz0) & TMASK;
    const unsigned i1 = (bx1 ^ hy0 ^ hz0) & TMASK;
    const unsigned i2 = (bx  ^ hy1 ^ hz0) & TMASK;
    const unsigned i3 = (bx1 ^ hy1 ^ hz0) & TMASK;
    const unsigned i4 = (bx  ^ hy0 ^ hz1) & TMASK;
    const unsigned i5 = (bx1 ^ hy0 ^ hz1) & TMASK;
    const unsigned i6 = (bx  ^ hy1 ^ hz1) & TMASK;
    const unsigned i7 = (bx1 ^ hy1 ^ hz1) & TMASK;

    __half2 t0, t1, t2, t3, t4, t5, t6, t7;
    if (f32mode) {
        const float2* __restrict__ tb = (const float2*)table_ + ((size_t)li << LOG2T);
        const float2 f0 = __ldg(tb + i0);
        const float2 f1 = __ldg(tb + i1);
        const float2 f2 = __ldg(tb + i2);
        const float2 f3 = __ldg(tb + i3);
        const float2 f4 = __ldg(tb + i4);
        const float2 f5 = __ldg(tb + i5);
        const float2 f6 = __ldg(tb + i6);
        const float2 f7 = __ldg(tb + i7);
        t0 = __floats2half2_rn(f0.x, f0.y);
        t1 = __floats2half2_rn(f1.x, f1.y);
        t2 = __floats2half2_rn(f2.x, f2.y);
        t3 = __floats2half2_rn(f3.x, f3.y);
        t4 = __floats2half2_rn(f4.x, f4.y);
        t5 = __floats2half2_rn(f5.x, f5.y);
        t6 = __floats2half2_rn(f6.x, f6.y);
        t7 = __floats2half2_rn(f7.x, f7.y);
    } else {
        const __half2* __restrict__ tb = (const __half2*)table_ + ((size_t)li << LOG2T);
        t0 = __ldg(tb + i0);  t1 = __ldg(tb + i1);
        t2 = __ldg(tb + i2);  t3 = __ldg(tb + i3);
        t4 = __ldg(tb + i4);  t5 = __ldg(tb + i5);
        t6 = __ldg(tb + i6);  t7 = __ldg(tb + i7);
    }

    const float ox = 1.f - dx, oy = 1.f - dy, oz = 1.f - dz;

    __half2 acc =              __hmul2(__float2half2_rn((ox * oy) * oz), t0);
    acc = __hadd2(acc, __hmul2(__float2half2_rn((dx * oy) * oz), t1));
    acc = __hadd2(acc, __hmul2(__float2half2_rn((ox * dy) * oz), t2));
    acc = __hadd2(acc, __hmul2(__float2half2_rn((dx * dy) * oz), t3));
    acc = __hadd2(acc, __hmul2(__float2half2_rn((ox * oy) * dz), t4));
    acc = __hadd2(acc, __hmul2(__float2half2_rn((dx * oy) * dz), t5));
    acc = __hadd2(acc, __hmul2(__float2half2_rn((ox * dy) * dz), t6));
    acc = __hadd2(acc, __hmul2(__float2half2_rn((dx * dy) * dz), t7));
    return acc;
}

// ---- levels 6..18 bid-phased over [p0, pend); groups 6..11 piggyback 0..5 ----
__global__ __launch_bounds__(256) void k_enc_phased(
    const float* __restrict__ xin,
    const void*  __restrict__ table_,
    const void*  __restrict__ W2_,
    int l0, int bpl, int p0, int pend, ResParams rp)
{
    const int li = l0 + blockIdx.x / bpl;
    const int pt = p0 + (blockIdx.x % bpl) * 256 + threadIdx.x;
    if (pt >= pend) return;
    const bool f32mode = probe_f32(W2_);

    const float px = __ldg(xin + 3 * pt + 0);
    const float py = __ldg(xin + 3 * pt + 1);
    const float pz = __ldg(xin + 3 * pt + 2);

    const __half2 acc = encode_level(px, py, pz, rp.r[li], table_, li, f32mode);
    __stcs(&g_feat[(size_t)li * NPTS + pt], acc);

    if (li < 12) {    // piggyback cache-resident level li-6 under DRAM stalls
        const int lo = li - 6;
        const __half2 acc2 = encode_level(px, py, pz, rp.r[lo], table_, lo, f32mode);
        __stcs(&g_feat[(size_t)lo * NPTS + pt], acc2);
    }
}

// ---- final: level 19 inline + MLP (R14 1pt/thread) over [p0, pend) ----
__global__ __launch_bounds__(256) void k_mlp_final(
    const float* __restrict__ xin,
    const void*  __restrict__ table_,
    const void*  __restrict__ W1_,
    const void*  __restrict__ W2_,
    void*        __restrict__ out_,
    int p0, int pend, ResParams rp)
{
    __shared__ __align__(16) float W1f[INDIM * HID];
    __shared__ __align__(16) float W2f[HID * 4];

    const bool f32mode = probe_f32(W2_);

    if (f32mode) {
        const float* W1s = (const float*)W1_;
        const float* W2s = (const float*)W2_;
        for (int i = threadIdx.x; i < INDIM * HID; i += 256) W1f[i] = W1s[i];
        for (int i = threadIdx.x; i < HID * 4;   i += 256) W2f[i] = W2s[i];
    } else {
        const __half* W1s = (const __half*)W1_;
        const __half* W2s = (const __half*)W2_;
        for (int i = threadIdx.x; i < INDIM * HID; i += 256) W1f[i] = __half2float(W1s[i]);
        for (int i = threadIdx.x; i < HID * 4;   i += 256) W2f[i] = __half2float(W2s[i]);
    }
    __syncthreads();

    const int pt = p0 + blockIdx.x * 256 + threadIdx.x;
    if (pt >= pend) return;

    const float px = __ldg(xin + 3 * pt + 0);
    const float py = __ldg(xin + 3 * pt + 1);
    const float pz = __ldg(xin + 3 * pt + 2);

    __half2 featp[NLVL];
    featp[19] = encode_level(px, py, pz, rp.r[19], table_, 19, f32mode);
    #pragma unroll
    for (int l = 0; l < 19; ++l)
        featp[l] = __ldcs(&g_feat[(size_t)l * NPTS + pt]);

    float oh[2][4];
    #pragma unroll
    for (int h = 0; h < 2; ++h) {
        const int hbase = h * 32;
        uint64_t o01 = pk2(0.f, 0.f), o23 = pk2(0.f, 0.f);

        #pragma unroll 1
        for (int cb = 0; cb < 32; cb += 8) {
            uint64_t hh2[4];
            #pragma unroll
            for (int j2 = 0; j2 < 4; ++j2) hh2[j2] = pk2(0.f, 0.f);

            #pragma unroll
            for (int lp = 0; lp < NLVL; ++lp) {
                const float2 fv = __half22float2(featp[lp]);
                const uint64_t fvx = pk2(fv.x, fv.x);
                const uint64_t fvy = pk2(fv.y, fv.y);
                const ulonglong2* __restrict__ w0p =
                    (const ulonglong2*)&W1f[(2 * lp)     * HID + hbase + cb];
                const ulonglong2* __restrict__ w1p =
                    (const ulonglong2*)&W1f[(2 * lp + 1) * HID + hbase + cb];
                const ulonglong2 a0 = w0p[0], a1 = w0p[1];
                const ulonglong2 b0 = w1p[0], b1 = w1p[1];
                ffma2(hh2[0], fvx, a0.x);  ffma2(hh2[0], fvy, b0.x);
                ffma2(hh2[1], fvx, a0.y);  ffma2(hh2[1], fvy, b0.y);
                ffma2(hh2[2], fvx, a1.x);  ffma2(hh2[2], fvy, b1.x);
                ffma2(hh2[3], fvx, a1.y);  ffma2(hh2[3], fvy, b1.y);
            }

            #pragma unroll
            for (int j2 = 0; j2 < 4; ++j2) {
                const float2 hp = upk2(hh2[j2]);
                #pragma unroll
                for (int k = 0; k < 2; ++k) {
                    const int jj = 2 * j2 + k;
                    const float hv = h_rt(fmaxf(k ? hp.y : hp.x, 0.f));
                    const uint64_t hv2 = pk2(hv, hv);
                    const ulonglong2 w2 =
                        *(const ulonglong2*)&W2f[(hbase + cb + jj) * 4];
                    ffma2(o01, hv2, w2.x);
                    ffma2(o23, hv2, w2.y);
                }
            }
        }
        const float2 a01 = upk2(o01), a23 = upk2(o23);
        oh[h][0] = a01.x; oh[h][1] = a01.y; oh[h][2] = a23.x; oh[h][3] = a23.y;
    }

    const float o0 = oh[0][0] + oh[1][0];
    const float o1 = oh[0][1] + oh[1][1];
    const float o2 = oh[0][2] + oh[1][2];
    const float o3 = oh[0][3] + oh[1][3];

    if (f32mode) {
        float4* o = (float4*)out_;
        o[pt] = make_float4(h_rt(o0), h_rt(o1), h_rt(o2), h_rt(o3));
    } else {
        __half2* o = (__half2*)out_;
        o[2 * pt + 0] = __halves2half2(__float2half_rn(o0), __float2half_rn(o1));
        o[2 * pt + 1] = __halves2half2(__float2half_rn(o2), __float2half_rn(o3));
    }
}

extern "C" void kernel_launch(void* const* d_in, const int* in_sizes, int n_in,
                              void* d_out, int out_size) {
    const float* x     = nullptr;  int x_elems = 0;
    const void*  table = nullptr;
    const void*  W1    = nullptr;
    const void*  W2    = nullptr;

    for (int i = 0; i < n_in; ++i) {
        const long long sz = in_sizes[i];
        if (sz == 671088640LL)      table = d_in[i];
        else if (sz == 1572864LL) { x = (const float*)d_in[i]; x_elems = (int)sz; }
        else if (sz == 2560LL)      W1 = d_in[i];
        else if (sz == 256LL)       W2 = d_in[i];
    }
    for (int i = 0; i < n_in; ++i) {
        const long long sz = in_sizes[i];
        if (!table && sz > 100000000LL) table = d_in[i];
        else if (!x && sz > 100000LL && sz <= 100000000LL) { x = (const float*)d_in[i]; x_elems = (int)sz; }
        else if (!W1 && sz > 1000LL && sz <= 100000LL) W1 = d_in[i];
        else if (!W2 && sz <= 1000LL) W2 = d_in[i];
    }

    int n = x_elems / 3;
    if (n > NPTS) n = NPTS;

    ResParams rp;
    for (int l = 0; l < NLVL; ++l)
        rp.r[l] = (float)floor(16.0 * pow(1.3819, (double)l));

    // Side stream + events: created on first call (the uncaptured correctness
    // run), reused thereafter. Event fork-join is the supported capture
    // pattern; no device memory is allocated.
    static cudaStream_t s2 = nullptr;
    static cudaEvent_t evFork = nullptr, evJoin = nullptr;
    if (s2 == nullptr) {
        cudaStreamCreateWithFlags(&s2, cudaStreamNonBlocking);
        cudaEventCreateWithFlags(&evFork, cudaEventDisableTiming);
        cudaEventCreateWithFlags(&evJoin, cudaEventDisableTiming);
    }

    // Two point chunks (256-aligned split).
    int n0 = ((n / 2) + 255) / 256 * 256;
    if (n0 > n) n0 = n;
    const int c0 = n0, c1 = n - n0;
    const int bpl0 = (c0 + 255) / 256;
    const int bpl1 = (c1 + 255) / 256;

    // chunk0 encode (levels 6-18 + 0-5 piggyback)
    k_enc_phased<<<13 * bpl0, 256>>>(x, table, W2, 6, bpl0, 0, n0, rp);

    // fork: mlp(chunk0) on side stream, overlapping phased(chunk1)
    cudaEventRecord(evFork, 0);
    cudaStreamWaitEvent(s2, evFork, 0);
    k_mlp_final<<<bpl0, 256, 0, s2>>>(x, table, W1, W2, d_out, 0, n0, rp);
    cudaEventRecord(evJoin, s2);

    if (c1 > 0) {
        k_enc_phased<<<13 * bpl1, 256>>>(x, table, W2, 6, bpl1, n0, n, rp);
        k_mlp_final<<<bpl1, 256>>>(x, table, W1, W2, d_out, n0, n, rp);
    }

    // join side stream back into the captured stream
    cudaStreamWaitEvent(0, evJoin, 0);
}

// round 17
// speedup vs baseline: 1.0515x; 1.0515x over previous
#include <cuda_runtime.h>
#include <cuda_fp16.h>
#include <math.h>
#include <stdint.h>

// R17: revert R16's chunk+overlap (chunking halves per-level gather reuse ->
// +100us DRAM traffic, measured). Back to the R14 champion structure:
//   phased(levels 6-18, piggyback 0-5) -> mlp(level 19 inline + MLP).
// Single change vs R14: the phased kernel processes TWO points per thread
// (up to 32 outstanding table loads) -- R14's phased ran ~4.7TB/s vs the
// 5.45TB/s this workload achieves elsewhere, i.e. partly latency-limited.
// Per-point math bit-identical -> rel_err stays 6.8627e-4.

#define NLVL   20
#define LOG2T  24
#define TMASK  ((1u << LOG2T) - 1u)
#define PRIME1 2654435761u
#define PRIME2 805459861u
#define INDIM  40
#define HID    64
#define NPTS   524288

struct ResParams { float r[NLVL]; };

__device__ __half2 g_feat[NLVL * NPTS];   // level-major scratch (42 MB)

__device__ __forceinline__ float h_rt(float v) {
    return __half2float(__float2half_rn(v));
}

__device__ __forceinline__ bool probe_f32(const void* W2_) {
    const float* w2p = (const float*)W2_;
    int votes = 0;
    #pragma unroll
    for (int i = 0; i < 8; ++i) {
        const float v = __ldg(w2p + i);
        if (isfinite(v) && fabsf(v) >= 2e-3f && fabsf(v) <= 8.0f) ++votes;
    }
    return votes >= 4;
}

// ---- f32x2 packed helpers (FFMA2) ----
__device__ __forceinline__ uint64_t pk2(float lo, float hi) {
    uint64_t r; asm("mov.b64 %0, {%1,%2};" : "=l"(r) : "f"(lo), "f"(hi)); return r;
}
__device__ __forceinline__ float2 upk2(uint64_t v) {
    float2 f; asm("mov.b64 {%0,%1}, %2;" : "=f"(f.x), "=f"(f.y) : "l"(v)); return f;
}
__device__ __forceinline__ void ffma2(uint64_t& d, uint64_t a, uint64_t b) {
    asm("fma.rn.f32x2 %0, %1, %2, %0;" : "+l"(d) : "l"(a), "l"(b));
}

// ---- one level's gather+interp (bit-identical reference fp16 chain) ----
__device__ __forceinline__ __half2 encode_level(
    float px, float py, float pz, float rf,
    const void* __restrict__ table_, int li, bool f32mode)
{
    const float fx = px * rf, fy = py * rf, fz = pz * rf;
    const float gx = floorf(fx), gy = floorf(fy), gz = floorf(fz);
    const float dx = fx - gx, dy = fy - gy, dz = fz - gz;
    const unsigned bx = (unsigned)gx;
    const unsigned by = (unsigned)gy;
    const unsigned bz = (unsigned)gz;
    const unsigned hy0 = by * PRIME1, hy1 = hy0 + PRIME1;
    const unsigned hz0 = bz * PRIME2, hz1 = hz0 + PRIME2;
    const unsigned bx1 = bx + 1u;

    const unsigned i0 = (bx  ^ hy0 ^ hz0) & TMASK;
    const unsigned i1 = (bx1 ^ hy0 ^ hz0) & TMASK;
    const unsigned i2 = (bx  ^ hy1 ^ hz0) & TMASK;
    const unsigned i3 = (bx1 ^ hy1 ^ hz0) & TMASK;
    const unsigned i4 = (bx  ^ hy0 ^ hz1) & TMASK;
    const unsigned i5 = (bx1 ^ hy0 ^ hz1) & TMASK;
    const unsigned i6 = (bx  ^ hy1 ^ hz1) & TMASK;
    const unsigned i7 = (bx1 ^ hy1 ^ hz1) & TMASK;

    __half2 t0, t1, t2, t3, t4, t5, t6, t7;
    if (f32mode) {
        const float2* __restrict__ tb = (const float2*)table_ + ((size_t)li << LOG2T);
        const float2 f0 = __ldg(tb + i0);
        const float2 f1 = __ldg(tb + i1);
        const float2 f2 = __ldg(tb + i2);
        const float2 f3 = __ldg(tb + i3);
        const float2 f4 = __ldg(tb + i4);
        const float2 f5 = __ldg(tb + i5);
        const float2 f6 = __ldg(tb + i6);
        const float2 f7 = __ldg(tb + i7);
        t0 = __floats2half2_rn(f0.x, f0.y);
        t1 = __floats2half2_rn(f1.x, f1.y);
        t2 = __floats2half2_rn(f2.x, f2.y);
        t3 = __floats2half2_rn(f3.x, f3.y);
        t4 = __floats2half2_rn(f4.x, f4.y);
        t5 = __floats2half2_rn(f5.x, f5.y);
        t6 = __floats2half2_rn(f6.x, f6.y);
        t7 = __floats2half2_rn(f7.x, f7.y);
    } else {
        const __half2* __restrict__ tb = (const __half2*)table_ + ((size_t)li << LOG2T);
        t0 = __ldg(tb + i0);  t1 = __ldg(tb + i1);
        t2 = __ldg(tb + i2);  t3 = __ldg(tb + i3);
        t4 = __ldg(tb + i4);  t5 = __ldg(tb + i5);
        t6 = __ldg(tb + i6);  t7 = __ldg(tb + i7);
    }

    const float ox = 1.f - dx, oy = 1.f - dy, oz = 1.f - dz;

    __half2 acc =              __hmul2(__float2half2_rn((ox * oy) * oz), t0);
    acc = __hadd2(acc, __hmul2(__float2half2_rn((dx * oy) * oz), t1));
    acc = __hadd2(acc, __hmul2(__float2half2_rn((ox * dy) * oz), t2));
    acc = __hadd2(acc, __hmul2(__float2half2_rn((dx * dy) * oz), t3));
    acc = __hadd2(acc, __hmul2(__float2half2_rn((ox * oy) * dz), t4));
    acc = __hadd2(acc, __hmul2(__float2half2_rn((dx * oy) * dz), t5));
    acc = __hadd2(acc, __hmul2(__float2half2_rn((ox * dy) * dz), t6));
    acc = __hadd2(acc, __hmul2(__float2half2_rn((dx * dy) * dz), t7));
    return acc;
}

// -- levels 6..18 bid-phased, 2 pts/thread; groups 6..11 piggyback 0..5 --
__global__ __launch_bounds__(256) void k_enc_phased(
    const float* __restrict__ xin,
    const void*  __restrict__ table_,
    const void*  __restrict__ W2_,
    int l0, int bpl, int n, ResParams rp)
{
    const int li   = l0 + blockIdx.x / bpl;
    const int base = (blockIdx.x % bpl) * 512 + threadIdx.x;
    const bool f32mode = probe_f32(W2_);
    const float rf = rp.r[li];
    const bool pig = (li < 12);
    const float rl = pig ? rp.r[li - 6] : 0.f;

    #pragma unroll
    for (int k = 0; k < 2; ++k) {
        const int pt = base + k * 256;
        if (pt >= n) return;
        const float px = __ldg(xin + 3 * pt + 0);
        const float py = __ldg(xin + 3 * pt + 1);
        const float pz = __ldg(xin + 3 * pt + 2);

        const __half2 acc = encode_level(px, py, pz, rf, table_, li, f32mode);
        __stcs(&g_feat[(size_t)li * NPTS + pt], acc);

        if (pig) {   // cache-resident low level under this CTA's DRAM stalls
            const int lo = li - 6;
            const __half2 acc2 = encode_level(px, py, pz, rl, table_, lo, f32mode);
            __stcs(&g_feat[(size_t)lo * NPTS + pt], acc2);
        }
    }
}

// -------- final: level 19 inline + MLP (R14 1pt/thread, FFMA2) --------
__global__ __launch_bounds__(256) void k_mlp_final(
    const float* __restrict__ xin,
    const void*  __restrict__ table_,
    const void*  __restrict__ W1_,
    const void*  __restrict__ W2_,
    void*        __restrict__ out_,
    int n, ResParams rp)
{
    __shared__ __align__(16) float W1f[INDIM * HID];
    __shared__ __align__(16) float W2f[HID * 4];

    const bool f32mode = probe_f32(W2_);

    if (f32mode) {
        const float* W1s = (const float*)W1_;
        const float* W2s = (const float*)W2_;
        for (int i = threadIdx.x; i < INDIM * HID; i += 256) W1f[i] = W1s[i];
        for (int i = threadIdx.x; i < HID * 4;   i += 256) W2f[i] = W2s[i];
    } else {
        const __half* W1s = (const __half*)W1_;
        const __half* W2s = (const __half*)W2_;
        for (int i = threadIdx.x; i < INDIM * HID; i += 256) W1f[i] = __half2float(W1s[i]);
        for (int i = threadIdx.x; i < HID * 4;   i += 256) W2f[i] = __half2float(W2s[i]);
    }
    __syncthreads();

    const int pt = blockIdx.x * 256 + threadIdx.x;
    if (pt >= n) return;

    const float px = __ldg(xin + 3 * pt + 0);
    const float py = __ldg(xin + 3 * pt + 1);
    const float pz = __ldg(xin + 3 * pt + 2);

    __half2 featp[NLVL];
    featp[19] = encode_level(px, py, pz, rp.r[19], table_, 19, f32mode);
    #pragma unroll
    for (int l = 0; l < 19; ++l)
        featp[l] = __ldcs(&g_feat[(size_t)l * NPTS + pt]);

    float oh[2][4];
    #pragma unroll
    for (int h = 0; h < 2; ++h) {
        const int hbase = h * 32;
        uint64_t o01 = pk2(0.f, 0.f), o23 = pk2(0.f, 0.f);

        #pragma unroll 1
        for (int cb = 0; cb < 32; cb += 8) {
            uint64_t hh2[4];
            #pragma unroll
            for (int j2 = 0; j2 < 4; ++j2) hh2[j2] = pk2(0.f, 0.f);

            #pragma unroll
            for (int lp = 0; lp < NLVL; ++lp) {
                const float2 fv = __half22float2(featp[lp]);
                const uint64_t fvx = pk2(fv.x, fv.x);
                const uint64_t fvy = pk2(fv.y, fv.y);
                const ulonglong2* __restrict__ w0p =
                    (const ulonglong2*)&W1f[(2 * lp)     * HID + hbase + cb];
                const ulonglong2* __restrict__ w1p =
                    (const ulonglong2*)&W1f[(2 * lp + 1) * HID + hbase + cb];
                const ulonglong2 a0 = w0p[0], a1 = w0p[1];
                const ulonglong2 b0 = w1p[0], b1 = w1p[1];
                ffma2(hh2[0], fvx, a0.x);  ffma2(hh2[0], fvy, b0.x);
                ffma2(hh2[1], fvx, a0.y);  ffma2(hh2[1], fvy, b0.y);
                ffma2(hh2[2], fvx, a1.x);  ffma2(hh2[2], fvy, b1.x);
                ffma2(hh2[3], fvx, a1.y);  ffma2(hh2[3], fvy, b1.y);
            }

            #pragma unroll
            for (int j2 = 0; j2 < 4; ++j2) {
                const float2 hp = upk2(hh2[j2]);
                #pragma unroll
                for (int k = 0; k < 2; ++k) {
                    const int jj = 2 * j2 + k;
                    const float hv = h_rt(fmaxf(k ? hp.y : hp.x, 0.f));
                    const uint64_t hv2 = pk2(hv, hv);
                    const ulonglong2 w2 =
                        *(const ulonglong2*)&W2f[(hbase + cb + jj) * 4];
                    ffma2(o01, hv2, w2.x);
                    ffma2(o23, hv2, w2.y);
                }
            }
        }
        const float2 a01 = upk2(o01), a23 = upk2(o23);
        oh[h][0] = a01.x; oh[h][1] = a01.y; oh[h][2] = a23.x; oh[h][3] = a23.y;
    }

    const float o0 = oh[0][0] + oh[1][0];
    const float o1 = oh[0][1] + oh[1][1];
    const float o2 = oh[0][2] + oh[1][2];
    const float o3 = oh[0][3] + oh[1][3];

    if (f32mode) {
        float4* o = (float4*)out_;
        o[pt] = make_float4(h_rt(o0), h_rt(o1), h_rt(o2), h_rt(o3));
    } else {
        __half2* o = (__half2*)out_;
        o[2 * pt + 0] = __halves2half2(__float2half_rn(o0), __float2half_rn(o1));
        o[2 * pt + 1] = __halves2half2(__float2half_rn(o2), __float2half_rn(o3));
    }
}

extern "C" void kernel_launch(void* const* d_in, const int* in_sizes, int n_in,
                              void* d_out, int out_size) {
    const float* x     = nullptr;  int x_elems = 0;
    const void*  table = nullptr;
    const void*  W1    = nullptr;
    const void*  W2    = nullptr;

    for (int i = 0; i < n_in; ++i) {
        const long long sz = in_sizes[i];
        if (sz == 671088640LL)      table = d_in[i];
        else if (sz == 1572864LL) { x = (const float*)d_in[i]; x_elems = (int)sz; }
        else if (sz == 2560LL)      W1 = d_in[i];
        else if (sz == 256LL)       W2 = d_in[i];
    }
    for (int i = 0; i < n_in; ++i) {
        const long long sz = in_sizes[i];
        if (!table && sz > 100000000LL) table = d_in[i];
        else if (!x && sz > 100000LL && sz <= 100000000LL) { x = (const float*)d_in[i]; x_elems = (int)sz; }
        else if (!W1 && sz > 1000LL && sz <= 100000LL) W1 = d_in[i];
        else if (!W2 && sz <= 1000LL) W2 = d_in[i];
    }

    int n = x_elems / 3;
    if (n > NPTS) n = NPTS;

    ResParams rp;
    for (int l = 0; l < NLVL; ++l)
        rp.r[l] = (float)floor(16.0 * pow(1.3819, (double)l));

    const int bpl  = (n + 255) / 256;    // mlp blocks (2048)
    const int bpl2 = (n + 511) / 512;    // phased blocks per level, 2 pt/thread

    k_enc_phased<<<13 * bpl2, 256>>>(x, table, W2, 6, bpl2, n, rp);  // lv 6-18 (+0-5)
    k_mlp_final<<<bpl, 256>>>(x, table, W1, W2, d_out, n, rp);       // lv 19 + MLP
}